// round 1
// baseline (speedup 1.0000x reference)
#include <cuda_runtime.h>
#include <math.h>

#define NN 50000
#define NE 800000

// ---------------- scratch (static device memory; no allocs) ----------------
__device__ int   g_cnt[NN];        // histogram counts, then CSR fill cursor
__device__ int   g_row[NN + 1];    // CSR row pointers (per dst node)
__device__ int   g_csr[NE];        // src ids grouped by dst
__device__ float g_he[NN];         // segment_sum(edge_feat, dst) -- layer invariant
__device__ float g_nbr[NN * 64];   // per-layer neighbor aggregation
__device__ float g_h0[NN * 64];    // ping
__device__ float g_h1[NN * 64];    // pong

// ---------------- CSR build ----------------
__global__ void k_zero() {
    int i = blockIdx.x * blockDim.x + threadIdx.x;
    if (i < NN) { g_cnt[i] = 0; g_he[i] = 0.0f; }
}

__global__ void k_hist(const int* __restrict__ dst, const float* __restrict__ ef) {
    int e = blockIdx.x * blockDim.x + threadIdx.x;
    if (e < NE) {
        int d = dst[e];
        atomicAdd(&g_cnt[d], 1);
        atomicAdd(&g_he[d], ef[e]);
    }
}

// single-block exclusive scan of g_cnt -> g_row; also primes g_cnt as cursor
__global__ void k_scan() {
    const int CH = 49;                       // 1024 * 49 >= 50000
    __shared__ int sums[1024];
    int t = threadIdx.x;
    int start = t * CH;
    int end   = min(start + CH, NN);
    int s = 0;
    for (int i = start; i < end; ++i) s += g_cnt[i];
    sums[t] = s;
    __syncthreads();
    #pragma unroll
    for (int off = 1; off < 1024; off <<= 1) {
        int mine = sums[t];
        int v = (t >= off) ? sums[t - off] : 0;
        __syncthreads();
        sums[t] = mine + v;
        __syncthreads();
    }
    int run = (t == 0) ? 0 : sums[t - 1];    // exclusive prefix
    for (int i = start; i < end; ++i) {
        int c = g_cnt[i];
        g_row[i] = run;
        g_cnt[i] = run;                      // cursor for fill
        run += c;
    }
    if (t == 1023) g_row[NN] = run;          // == NE
}

__global__ void k_fill(const int* __restrict__ src, const int* __restrict__ dst) {
    int e = blockIdx.x * blockDim.x + threadIdx.x;
    if (e < NE) {
        int d = dst[e];
        int p = atomicAdd(&g_cnt[d], 1);
        g_csr[p] = src[e];
    }
}

// ---------------- neighbor aggregation: warp per node ----------------
// lane l accumulates features 2l, 2l+1 (float2 per edge -> 256B coalesced row reads,
// all L2-resident since h is 12.8MB)
__global__ void k_agg(const float* __restrict__ h) {
    int w = (blockIdx.x * blockDim.x + threadIdx.x) >> 5;
    if (w >= NN) return;
    int lane = threadIdx.x & 31;
    int s = g_row[w], e = g_row[w + 1];
    float ax = 0.0f, ay = 0.0f;
    for (int j = s; j < e; ++j) {
        int u = __ldg(&g_csr[j]);
        float2 v = *reinterpret_cast<const float2*>(h + (u << 6) + (lane << 1));
        ax += v.x; ay += v.y;
    }
    float2 o; o.x = ax; o.y = ay;
    *reinterpret_cast<float2*>(g_nbr + (w << 6) + (lane << 1)) = o;
}

// ---------------- fused concat+GEMM+bias+act, 64-wide layers ----------------
// out[m][n] = act( b[n] + he[m]*W[n][128] + sum_k<64 h[m][k]*W[n][k]
//                                         + sum_k<64 nbr[m][k]*W[n][64+k] )
// BM=64 nodes, BN=64 outputs, K=128 staged whole in smem. 128 threads,
// thread tile 4x8 with strided m (row+16i) / n (col+8j) -> conflict-free LDS.
// ACT: 0 none, 1 relu, 2 sigmoid
template <int ACT>
__global__ void __launch_bounds__(128) k_gemm64(
    const float* __restrict__ h,
    const float* __restrict__ W,      // [64][129]
    const float* __restrict__ bias,   // [64]
    float* __restrict__ out) {
    __shared__ float As[64 * 132];    // [m][k] row stride 132 (16B aligned, bank-skewed)
    __shared__ float Bs[64 * 132];    // [n][k]
    int tid = threadIdx.x;
    int m0 = blockIdx.x * 64;

    // stage A: k<64 from h, k>=64 from g_nbr (the concat)
    #pragma unroll
    for (int t = 0; t < 16; ++t) {
        int u  = tid + t * 128;       // 2048 float4s
        int m  = u >> 5;
        int kq = u & 31;
        int gm = m0 + m;
        float4 v = make_float4(0.f, 0.f, 0.f, 0.f);
        if (gm < NN) {
            const float* src = (kq < 16) ? (h + gm * 64 + kq * 4)
                                         : (g_nbr + gm * 64 + (kq - 16) * 4);
            v = *reinterpret_cast<const float4*>(src);
        }
        *reinterpret_cast<float4*>(&As[m * 132 + kq * 4]) = v;
    }
    // stage B: W rows are 129 floats (odd) -> scalar loads, L1-resident after wave 1
    #pragma unroll
    for (int t = 0; t < 64; ++t) {
        int u = tid + t * 128;        // 8192 floats
        int n = u >> 7;
        int k = u & 127;
        Bs[n * 132 + k] = W[n * 129 + k];
    }
    __syncthreads();

    int row = tid >> 3;               // 0..15
    int col = tid & 7;                // 0..7
    float acc[4][8];
    #pragma unroll
    for (int i = 0; i < 4; ++i)
        #pragma unroll
        for (int j = 0; j < 8; ++j) acc[i][j] = 0.0f;

    #pragma unroll 8
    for (int kq = 0; kq < 32; ++kq) {
        float4 a[4], bb[8];
        #pragma unroll
        for (int i = 0; i < 4; ++i)
            a[i] = *reinterpret_cast<const float4*>(&As[(row + 16 * i) * 132 + kq * 4]);
        #pragma unroll
        for (int j = 0; j < 8; ++j)
            bb[j] = *reinterpret_cast<const float4*>(&Bs[(col + 8 * j) * 132 + kq * 4]);
        #pragma unroll
        for (int i = 0; i < 4; ++i)
            #pragma unroll
            for (int j = 0; j < 8; ++j) {
                acc[i][j] += a[i].x * bb[j].x;
                acc[i][j] += a[i].y * bb[j].y;
                acc[i][j] += a[i].z * bb[j].z;
                acc[i][j] += a[i].w * bb[j].w;
            }
    }

    // epilogue: he rank-1 column + bias + activation
    #pragma unroll
    for (int i = 0; i < 4; ++i) {
        int m = m0 + row + 16 * i;
        if (m >= NN) continue;
        float hev = g_he[m];
        #pragma unroll
        for (int j = 0; j < 8; ++j) {
            int n = col + 8 * j;
            float v = acc[i][j] + bias[n] + hev * __ldg(&W[n * 129 + 128]);
            if (ACT == 1)      v = fmaxf(v, 0.0f);
            else if (ACT == 2) v = 1.0f / (1.0f + expf(-v));
            out[m * 64 + n] = v;
        }
    }
}

// ---------------- final layer: 2 outputs, thread per node ----------------
__global__ void k_gemm2(const float* __restrict__ h,
                        const float* __restrict__ W2,   // [2][129]
                        const float* __restrict__ b2,
                        float* __restrict__ out) {
    int m = blockIdx.x * blockDim.x + threadIdx.x;
    if (m >= NN) return;
    float hev = g_he[m];
    float a0 = b2[0] + hev * __ldg(&W2[128]);
    float a1 = b2[1] + hev * __ldg(&W2[129 + 128]);
    const float* hr = h + m * 64;
    const float* nr = g_nbr + m * 64;
    #pragma unroll
    for (int k = 0; k < 64; ++k) {
        float x = hr[k];
        a0 += x * __ldg(&W2[k]);
        a1 += x * __ldg(&W2[129 + k]);
    }
    #pragma unroll
    for (int k = 0; k < 64; ++k) {
        float x = nr[k];
        a0 += x * __ldg(&W2[64 + k]);
        a1 += x * __ldg(&W2[129 + 64 + k]);
    }
    out[m * 2]     = a0;
    out[m * 2 + 1] = a1;
}

// ---------------- driver ----------------
extern "C" void kernel_launch(void* const* d_in, const int* in_sizes, int n_in,
                              void* d_out, int out_size) {
    const float* node_feat = (const float*)d_in[0];
    const float* edge_feat = (const float*)d_in[1];
    const int*   src       = (const int*)d_in[2];
    const int*   dst       = (const int*)d_in[3];
    const float* W1        = (const float*)d_in[4];
    const float* b1        = (const float*)d_in[5];
    const float* Wmid      = (const float*)d_in[6];   // [5][64][129]
    const float* bmid      = (const float*)d_in[7];   // [5][64]
    const float* W2        = (const float*)d_in[8];
    const float* b2        = (const float*)d_in[9];
    float* out = (float*)d_out;

    float *h0, *h1;
    cudaGetSymbolAddress((void**)&h0, g_h0);
    cudaGetSymbolAddress((void**)&h1, g_h1);

    const int EB = (NE + 255) / 256;
    const int AB = (NN * 32 + 255) / 256;  // one warp per node
    const int GB = (NN + 63) / 64;

    // CSR build + he_aggr (once; reused by all 7 convs)
    k_zero<<<(NN + 255) / 256, 256>>>();
    k_hist<<<EB, 256>>>(dst, edge_feat);
    k_scan<<<1, 1024>>>();
    k_fill<<<EB, 256>>>(src, dst);

    // layer 1: 64->64, relu
    k_agg<<<AB, 256>>>(node_feat);
    k_gemm64<1><<<GB, 128>>>(node_feat, W1, b1, h0);

    // 5 mid layers: relu x4, sigmoid on last
    float* cur = h0;
    float* nxt = h1;
    for (int i = 0; i < 5; ++i) {
        k_agg<<<AB, 256>>>(cur);
        const float* Wi = Wmid + i * 64 * 129;
        const float* bi = bmid + i * 64;
        if (i < 4) k_gemm64<1><<<GB, 128>>>(cur, Wi, bi, nxt);
        else       k_gemm64<2><<<GB, 128>>>(cur, Wi, bi, nxt);
        float* t = cur; cur = nxt; nxt = t;
    }

    // final layer: 64->2, no activation
    k_agg<<<AB, 256>>>(cur);
    k_gemm2<<<(NN + 127) / 128, 128>>>(cur, W2, b2, out);
}

// round 2
// speedup vs baseline: 1.0458x; 1.0458x over previous
#include <cuda_runtime.h>
#include <math.h>

#define NN 50000
#define NE 800000

// ---------------- scratch (static device memory; no allocs) ----------------
__device__ int   g_cnt[NN];        // histogram counts, then CSR fill cursor
__device__ int   g_row[NN + 1];    // CSR row pointers (per dst node)
__device__ int   g_csr[NE];        // src ids grouped by dst
__device__ float g_he[NN];         // segment_sum(edge_feat, dst) -- layer invariant
__device__ float g_h0[NN * 64];    // ping
__device__ float g_h1[NN * 64];    // pong

// ---------------- CSR build ----------------
__global__ void k_zero() {
    int i = blockIdx.x * blockDim.x + threadIdx.x;
    if (i < NN) { g_cnt[i] = 0; g_he[i] = 0.0f; }
}

__global__ void k_hist(const int* __restrict__ dst, const float* __restrict__ ef) {
    int e = blockIdx.x * blockDim.x + threadIdx.x;
    if (e < NE) {
        int d = dst[e];
        atomicAdd(&g_cnt[d], 1);
        atomicAdd(&g_he[d], ef[e]);
    }
}

// single-block exclusive scan of g_cnt -> g_row; also primes g_cnt as cursor
__global__ void k_scan() {
    const int CH = 49;                       // 1024 * 49 >= 50000
    __shared__ int sums[1024];
    int t = threadIdx.x;
    int start = t * CH;
    int end   = min(start + CH, NN);
    int s = 0;
    for (int i = start; i < end; ++i) s += g_cnt[i];
    sums[t] = s;
    __syncthreads();
    #pragma unroll
    for (int off = 1; off < 1024; off <<= 1) {
        int mine = sums[t];
        int v = (t >= off) ? sums[t - off] : 0;
        __syncthreads();
        sums[t] = mine + v;
        __syncthreads();
    }
    int run = (t == 0) ? 0 : sums[t - 1];    // exclusive prefix
    for (int i = start; i < end; ++i) {
        int c = g_cnt[i];
        g_row[i] = run;
        g_cnt[i] = run;                      // cursor for fill
        run += c;
    }
    if (t == 1023) g_row[NN] = run;          // == NE
}

__global__ void k_fill(const int* __restrict__ src, const int* __restrict__ dst) {
    int e = blockIdx.x * blockDim.x + threadIdx.x;
    if (e < NE) {
        int d = dst[e];
        int p = atomicAdd(&g_cnt[d], 1);
        g_csr[p] = src[e];
    }
}

// ---------------- fused agg + concat + GEMM + bias + act ----------------
// Per block: 64 nodes. Phase 1: stage h rows + W into smem, warp-per-node
// neighbor aggregation directly into the k>=64 half of the A tile (with
// chunked csr-index prefetch to break the idx->data dependent chain).
// Phase 2: 64x64x128 smem GEMM, 256 threads, 4x4 register tile.
// ACT: 1 relu, 2 sigmoid
#define AS_STRIDE 132
#define SMEM_FUSED ((64 * AS_STRIDE * 2) * 4 + 8 * 32 * 4)

template <int ACT>
__global__ void __launch_bounds__(256) k_fused(
    const float* __restrict__ h,
    const float* __restrict__ W,      // [64][129]
    const float* __restrict__ bias,   // [64]
    float* __restrict__ out) {
    extern __shared__ float smem[];
    float* As = smem;                       // [64][132]  (h | nbr)
    float* Bs = As + 64 * AS_STRIDE;        // [64][132]  (129 cols of W)
    int*   sidx = (int*)(Bs + 64 * AS_STRIDE);  // [8][32] idx prefetch buffers

    int tid  = threadIdx.x;
    int w    = tid >> 5;
    int lane = tid & 31;
    int m0   = blockIdx.x * 64;

    // stage h half of A: 64 rows x 16 float4
    #pragma unroll
    for (int t = 0; t < 4; ++t) {
        int u  = tid + t * 256;
        int m  = u >> 4;
        int kq = u & 15;
        int gm = m0 + m;
        float4 v = make_float4(0.f, 0.f, 0.f, 0.f);
        if (gm < NN) v = *reinterpret_cast<const float4*>(h + gm * 64 + kq * 4);
        *reinterpret_cast<float4*>(&As[m * AS_STRIDE + kq * 4]) = v;
    }
    // stage W (all 129 cols, incl. he coefficient at k=128)
    for (int u = tid; u < 64 * 129; u += 256) {
        int n = u / 129;
        int k = u - n * 129;
        Bs[n * AS_STRIDE + k] = W[u];
    }

    // neighbor aggregation: warp w handles nodes w, w+8, ..., w+56
    #pragma unroll
    for (int i = 0; i < 8; ++i) {
        int mloc = w + 8 * i;
        int gm   = m0 + mloc;
        float ax = 0.0f, ay = 0.0f;
        if (gm < NN) {
            int s = g_row[gm], e = g_row[gm + 1];
            for (int c = s; c < e; c += 32) {
                int n = min(32, e - c);
                if (lane < n) sidx[w * 32 + lane] = g_csr[c + lane];
                __syncwarp();
                for (int t = 0; t < n; ++t) {
                    int u = sidx[w * 32 + t];
                    float2 v = *reinterpret_cast<const float2*>(h + (u << 6) + (lane << 1));
                    ax += v.x; ay += v.y;
                }
                __syncwarp();
            }
        }
        *reinterpret_cast<float2*>(&As[mloc * AS_STRIDE + 64 + (lane << 1)])
            = make_float2(ax, ay);
    }
    __syncthreads();

    // GEMM: 64x64, K=128. thread tile 4x4, strided (m = row+16i, n = col+16j)
    int row = tid >> 4;               // 0..15
    int col = tid & 15;               // 0..15
    float acc[4][4];
    #pragma unroll
    for (int i = 0; i < 4; ++i)
        #pragma unroll
        for (int j = 0; j < 4; ++j) acc[i][j] = 0.0f;

    #pragma unroll 8
    for (int kq = 0; kq < 32; ++kq) {
        float4 a[4], bb[4];
        #pragma unroll
        for (int i = 0; i < 4; ++i)
            a[i] = *reinterpret_cast<const float4*>(&As[(row + 16 * i) * AS_STRIDE + kq * 4]);
        #pragma unroll
        for (int j = 0; j < 4; ++j)
            bb[j] = *reinterpret_cast<const float4*>(&Bs[(col + 16 * j) * AS_STRIDE + kq * 4]);
        #pragma unroll
        for (int i = 0; i < 4; ++i)
            #pragma unroll
            for (int j = 0; j < 4; ++j) {
                acc[i][j] += a[i].x * bb[j].x;
                acc[i][j] += a[i].y * bb[j].y;
                acc[i][j] += a[i].z * bb[j].z;
                acc[i][j] += a[i].w * bb[j].w;
            }
    }

    // epilogue: he rank-1 column + bias + activation
    #pragma unroll
    for (int i = 0; i < 4; ++i) {
        int m = m0 + row + 16 * i;
        if (m >= NN) continue;
        float hev = g_he[m];
        #pragma unroll
        for (int j = 0; j < 4; ++j) {
            int n = col + 16 * j;
            float v = acc[i][j] + __ldg(&bias[n]) + hev * Bs[n * AS_STRIDE + 128];
            if (ACT == 1)      v = fmaxf(v, 0.0f);
            else if (ACT == 2) v = 1.0f / (1.0f + expf(-v));
            out[m * 64 + n] = v;
        }
    }
}

// ---------------- final layer fused: agg + 2-output GEMM ----------------
__global__ void __launch_bounds__(256) k_final(
    const float* __restrict__ h,
    const float* __restrict__ W2,   // [2][129]
    const float* __restrict__ b2,
    float* __restrict__ out) {
    __shared__ float As[64 * AS_STRIDE];
    __shared__ int   sidx[8 * 32];

    int tid  = threadIdx.x;
    int w    = tid >> 5;
    int lane = tid & 31;
    int m0   = blockIdx.x * 64;

    // stage h half of A
    #pragma unroll
    for (int t = 0; t < 4; ++t) {
        int u  = tid + t * 256;
        int m  = u >> 4;
        int kq = u & 15;
        int gm = m0 + m;
        float4 v = make_float4(0.f, 0.f, 0.f, 0.f);
        if (gm < NN) v = *reinterpret_cast<const float4*>(h + gm * 64 + kq * 4);
        *reinterpret_cast<float4*>(&As[m * AS_STRIDE + kq * 4]) = v;
    }

    // aggregation
    #pragma unroll
    for (int i = 0; i < 8; ++i) {
        int mloc = w + 8 * i;
        int gm   = m0 + mloc;
        float ax = 0.0f, ay = 0.0f;
        if (gm < NN) {
            int s = g_row[gm], e = g_row[gm + 1];
            for (int c = s; c < e; c += 32) {
                int n = min(32, e - c);
                if (lane < n) sidx[w * 32 + lane] = g_csr[c + lane];
                __syncwarp();
                for (int t = 0; t < n; ++t) {
                    int u = sidx[w * 32 + t];
                    float2 v = *reinterpret_cast<const float2*>(h + (u << 6) + (lane << 1));
                    ax += v.x; ay += v.y;
                }
                __syncwarp();
            }
        }
        *reinterpret_cast<float2*>(&As[mloc * AS_STRIDE + 64 + (lane << 1)])
            = make_float2(ax, ay);
    }
    __syncthreads();

    // 2-wide output: thread i<128 -> node i>>1, class i&1
    if (tid < 128) {
        int mloc = tid >> 1;
        int cls  = tid & 1;
        int m    = m0 + mloc;
        if (m < NN) {
            const float* Wr = W2 + cls * 129;
            float a = __ldg(&b2[cls]) + g_he[m] * __ldg(&Wr[128]);
            #pragma unroll
            for (int kq = 0; kq < 32; ++kq) {
                float4 x = *reinterpret_cast<const float4*>(&As[mloc * AS_STRIDE + kq * 4]);
                a += x.x * __ldg(&Wr[kq * 4 + 0]);
                a += x.y * __ldg(&Wr[kq * 4 + 1]);
                a += x.z * __ldg(&Wr[kq * 4 + 2]);
                a += x.w * __ldg(&Wr[kq * 4 + 3]);
            }
            out[m * 2 + cls] = a;
        }
    }
}

// ---------------- driver ----------------
extern "C" void kernel_launch(void* const* d_in, const int* in_sizes, int n_in,
                              void* d_out, int out_size) {
    const float* node_feat = (const float*)d_in[0];
    const float* edge_feat = (const float*)d_in[1];
    const int*   src       = (const int*)d_in[2];
    const int*   dst       = (const int*)d_in[3];
    const float* W1        = (const float*)d_in[4];
    const float* b1        = (const float*)d_in[5];
    const float* Wmid      = (const float*)d_in[6];   // [5][64][129]
    const float* bmid      = (const float*)d_in[7];   // [5][64]
    const float* W2        = (const float*)d_in[8];
    const float* b2        = (const float*)d_in[9];
    float* out = (float*)d_out;

    float *h0, *h1;
    cudaGetSymbolAddress((void**)&h0, g_h0);
    cudaGetSymbolAddress((void**)&h1, g_h1);

    static bool attr_done = false;
    if (!attr_done) {
        cudaFuncSetAttribute(k_fused<1>, cudaFuncAttributeMaxDynamicSharedMemorySize, SMEM_FUSED);
        cudaFuncSetAttribute(k_fused<2>, cudaFuncAttributeMaxDynamicSharedMemorySize, SMEM_FUSED);
        attr_done = true;
    }

    const int EB = (NE + 255) / 256;
    const int GB = (NN + 63) / 64;

    // CSR build + he_aggr (once; reused by all 7 convs)
    k_zero<<<(NN + 255) / 256, 256>>>();
    k_hist<<<EB, 256>>>(dst, edge_feat);
    k_scan<<<1, 1024>>>();
    k_fill<<<EB, 256>>>(src, dst);

    // layer 1: 64->64, relu
    k_fused<1><<<GB, 256, SMEM_FUSED>>>(node_feat, W1, b1, h0);

    // 5 mid layers: relu x4, sigmoid on last
    float* cur = h0;
    float* nxt = h1;
    for (int i = 0; i < 5; ++i) {
        const float* Wi = Wmid + i * 64 * 129;
        const float* bi = bmid + i * 64;
        if (i < 4) k_fused<1><<<GB, 256, SMEM_FUSED>>>(cur, Wi, bi, nxt);
        else       k_fused<2><<<GB, 256, SMEM_FUSED>>>(cur, Wi, bi, nxt);
        float* t = cur; cur = nxt; nxt = t;
    }

    // final layer: agg + 64->2 GEMM fused
    k_final<<<GB, 256>>>(cur, W2, b2, out);
}